// round 9
// baseline (speedup 1.0000x reference)
#include <cuda_runtime.h>

// 3D inverse Haar DWT via local 2x2x2 signed butterfly.
// S (Haar synthesis) == out[2m] = r*(lo[m]-hi[m]); out[2m+1] = r*(lo[m]+hi[m]).
//
// R8 = R2 body in a PERSISTENT grid-stride loop:
//   * grid = 8 CTAs x 148 SMs = 1184 blocks, each thread handles ~7 voxels.
//     Removes the 7 wave transitions / CTA churn behind achieved occ=74.9%.
//   * unroll 2: ptxas hoists next iteration's 4 independent LDG.128 above the
//     current iteration's stores -> sustained MLP without R5's register blowup.
// Everything else identical to the R2 winner (4x LDG.128 nc, 4x STG.128).

#define HALF_N 128
#define TOTAL_VOX (HALF_N * HALF_N * HALF_N)   // 2,097,152
#define R3C 0.35355339059327378f               // 2^{-3/2}
#define NUM_SMS 148
#define CTAS_PER_SM 8
#define NBLOCKS (NUM_SMS * CTAS_PER_SM)        // 1184

__global__ void __launch_bounds__(256, CTAS_PER_SM)
idwt3d_haar_kernel(const float* __restrict__ in, float* __restrict__ out)
{
    const int stride = NBLOCKS * 256;
    #pragma unroll 2
    for (int t = blockIdx.x * 256 + threadIdx.x; t < TOTAL_VOX; t += stride) {
        const int k = t & (HALF_N - 1);
        const int j = (t >> 7) & (HALF_N - 1);
        const int i = t >> 14;

        // Load 16 contiguous floats: 8 subbands x 2 channels.
        const float4* __restrict__ p =
            reinterpret_cast<const float4*>(in) + (size_t)t * 4;
        float4 q0 = __ldg(p + 0);
        float4 q1 = __ldg(p + 1);
        float4 q2 = __ldg(p + 2);
        float4 q3 = __ldg(p + 3);

        // v[sb] = {ch0, ch1}, sb = s1*4 + s2*2 + s3  (L=0, H=1 per axis)
        float2 v[8];
        v[0] = make_float2(q0.x, q0.y); v[1] = make_float2(q0.z, q0.w);
        v[2] = make_float2(q1.x, q1.y); v[3] = make_float2(q1.z, q1.w);
        v[4] = make_float2(q2.x, q2.y); v[5] = make_float2(q2.z, q2.w);
        v[6] = make_float2(q3.x, q3.y); v[7] = make_float2(q3.z, q3.w);

        // Stage 1: axis-3
        float2 u[8];
        #pragma unroll
        for (int g = 0; g < 4; g++) {
            float2 L = v[2 * g], H = v[2 * g + 1];
            u[2 * g + 0] = make_float2(L.x - H.x, L.y - H.y);
            u[2 * g + 1] = make_float2(L.x + H.x, L.y + H.y);
        }
        // Stage 2: axis-2
        float2 w[8];
        #pragma unroll
        for (int s1 = 0; s1 < 2; s1++)
            #pragma unroll
            for (int d = 0; d < 2; d++) {
                float2 L = u[s1 * 4 + d], H = u[s1 * 4 + 2 + d];
                w[s1 * 4 + d]     = make_float2(L.x - H.x, L.y - H.y);
                w[s1 * 4 + 2 + d] = make_float2(L.x + H.x, L.y + H.y);
            }
        // Stage 3: axis-1 (+ r^3 scale)
        float2 rr[8];
        #pragma unroll
        for (int e = 0; e < 4; e++) {
            float2 L = w[e], H = w[4 + e];
            rr[e]     = make_float2(R3C * (L.x - H.x), R3C * (L.y - H.y));
            rr[4 + e] = make_float2(R3C * (L.x + H.x), R3C * (L.y + H.y));
        }

        // Store: out[(2i+a), (2j+b), 2k+d, c]; for fixed (a,b) -> one float4.
        #pragma unroll
        for (int a = 0; a < 2; a++)
            #pragma unroll
            for (int b = 0; b < 2; b++) {
                const size_t off =
                    ((size_t)(2 * i + a) * 256 + (size_t)(2 * j + b)) * 512
                    + (size_t)(4 * k);
                float2 e0 = rr[a * 4 + b * 2 + 0];
                float2 e1 = rr[a * 4 + b * 2 + 1];
                *reinterpret_cast<float4*>(out + off) =
                    make_float4(e0.x, e0.y, e1.x, e1.y);
            }
    }
}

extern "C" void kernel_launch(void* const* d_in, const int* in_sizes, int n_in,
                              void* d_out, int out_size)
{
    const float* x = (const float*)d_in[0];   // [1,128,128,128,16]
    float* out = (float*)d_out;               // [1,256,256,256,2]

    idwt3d_haar_kernel<<<NBLOCKS, 256>>>(x, out);
}